// round 14
// baseline (speedup 1.0000x reference)
#include <cuda_runtime.h>
#include <cuda_fp16.h>
#include <cstdint>
#include <math.h>

// Problem constants
#define BB 4
#define TT 2048
#define CC 1024
#define HH 16
#define DD 64
#define MM (BB*TT)          // 8192
#define NQKV (3*CC)         // 3072

// ---------------------------------------------------------------------------
// Scratch (__device__ globals; no allocation allowed)
// ---------------------------------------------------------------------------
__device__ __half g_Qh[BB*HH*TT*DD];          // fp16, pre-scaled by 0.125*log2(e)
__device__ __half g_Kh[BB*HH*TT*DD];
__device__ __half g_Vh[BB*HH*TT*DD];
__device__ __half g_Xh[MM*CC];                // x as fp16
__device__ __half g_Wqh[NQKV*CC];             // w_qkv fp16
__device__ __half g_Wph[CC*CC];               // w_proj fp16
__device__ __half g_Oh[MM*CC];                // attn out fp16, [B*T, C]

// ---------------------------------------------------------------------------
// helpers
// ---------------------------------------------------------------------------
__device__ __forceinline__ uint32_t smem_u32(const void* p) {
    uint32_t a;
    asm("{ .reg .u64 t; cvta.to.shared.u64 t, %1; cvt.u32.u64 %0, t; }" : "=r"(a) : "l"(p));
    return a;
}
__device__ __forceinline__ void ldsm_x4(uint32_t& r0, uint32_t& r1, uint32_t& r2,
                                        uint32_t& r3, uint32_t addr) {
    asm volatile("ldmatrix.sync.aligned.m8n8.x4.shared.b16 {%0,%1,%2,%3}, [%4];"
                 : "=r"(r0), "=r"(r1), "=r"(r2), "=r"(r3) : "r"(addr));
}
__device__ __forceinline__ void ldsm_x4_t(uint32_t& r0, uint32_t& r1, uint32_t& r2,
                                          uint32_t& r3, uint32_t addr) {
    asm volatile("ldmatrix.sync.aligned.m8n8.x4.trans.shared.b16 {%0,%1,%2,%3}, [%4];"
                 : "=r"(r0), "=r"(r1), "=r"(r2), "=r"(r3) : "r"(addr));
}
__device__ __forceinline__ void mma_f16(float* c, const uint32_t* a, const uint32_t* b) {
    asm volatile("mma.sync.aligned.m16n8k16.row.col.f32.f16.f16.f32 "
                 "{%0,%1,%2,%3}, {%4,%5,%6,%7}, {%8,%9}, {%0,%1,%2,%3};"
                 : "+f"(c[0]), "+f"(c[1]), "+f"(c[2]), "+f"(c[3])
                 : "r"(a[0]), "r"(a[1]), "r"(a[2]), "r"(a[3]), "r"(b[0]), "r"(b[1]));
}
__device__ __forceinline__ void cp16(uint32_t dst, const void* src) {
    asm volatile("cp.async.cg.shared.global [%0], [%1], 16;" :: "r"(dst), "l"(src));
}
#define CP_COMMIT() asm volatile("cp.async.commit_group;" ::: "memory")
#define CP_WAIT(N)  asm volatile("cp.async.wait_group %0;" :: "n"(N) : "memory")

__device__ __forceinline__ uint32_t packf2(float x, float y) {
    __half2 t = __floats2half2_rn(x, y);   // x -> low half
    return *reinterpret_cast<uint32_t*>(&t);
}

// ---------------------------------------------------------------------------
// fused fp32 -> fp16 conversion (x, w_qkv, w_proj in one launch)
// ---------------------------------------------------------------------------
#define N4_X    (MM*CC/4)      // 2097152
#define N4_WQ   (NQKV*CC/4)    //  786432
#define N4_WP   (CC*CC/4)      //  262144
#define N4_ALL  (N4_X + N4_WQ + N4_WP)

__global__ __launch_bounds__(256) void convert_all_kernel(
    const float* __restrict__ x, const float* __restrict__ wq,
    const float* __restrict__ wp)
{
    int i = blockIdx.x * blockDim.x + threadIdx.x;
    if (i >= N4_ALL) return;
    const float* src; __half* dst; int j;
    if (i < N4_X)               { src = x;  dst = g_Xh;  j = i; }
    else if (i < N4_X + N4_WQ)  { src = wq; dst = g_Wqh; j = i - N4_X; }
    else                        { src = wp; dst = g_Wph; j = i - N4_X - N4_WQ; }
    float4 v = ((const float4*)src)[j];
    uint2 o;
    o.x = packf2(v.x, v.y);
    o.y = packf2(v.z, v.w);
    ((uint2*)dst)[j] = o;
}

// ---------------------------------------------------------------------------
// HMMA fp16 single-pass GEMM (unchanged from R13): C = Ah*Bh
// 256 threads / 8 warps, warp 32x64, CTA 128x128, BK=64, 3-stage, 2 CTA/SM.
// ---------------------------------------------------------------------------
#define BKG 64
#define LDG_ 72
#define TILEA (128*LDG_)
#define TILEB (128*LDG_)
#define STAGEG (TILEA + TILEB)            // 18432 halves
#define NSTG 3
#define GEMM_SMEM_BYTES (NSTG*STAGEG*2)   // 110592 B
#define GEMM_THREADS 256
#define LOG2E 1.44269504088896f

template<int MODE>
__global__ __launch_bounds__(GEMM_THREADS, 2) void mma_gemm_kernel(
    const __half* __restrict__ Ah, const __half* __restrict__ Bh,
    float* __restrict__ out)
{
    extern __shared__ __half sm[];
    const uint32_t smb = smem_u32(sm);
    const int tid = threadIdx.x;
    const int lane = tid & 31, wid = tid >> 5;
    const int wm = (wid >> 1) * 32;
    const int wn = (wid & 1) * 64;
    const int n0 = blockIdx.x * 128;
    const int m0 = blockIdx.y * 128;

    const __half* Asrc = Ah + (size_t)m0 * CC;
    const __half* Bsrc = Bh + (size_t)n0 * CC;

    const int NCH = CC / BKG;   // 16

    float acc[2][8][4];
    #pragma unroll
    for (int a = 0; a < 2; a++)
        #pragma unroll
        for (int b = 0; b < 8; b++)
            #pragma unroll
            for (int c = 0; c < 4; c++) acc[a][b][c] = 0.0f;

    const int a_m = ((lane >> 3) & 1) * 8 + (lane & 7);
    const int a_k = (lane >> 4) * 8;
    const int b_n = (lane >> 4) * 8 + (lane & 7);
    const int b_k = ((lane >> 3) & 1) * 8;

    auto issue_chunk = [&](int st, int ch) {
        const uint32_t sbase = smb + (uint32_t)st * (STAGEG * 2);
        const int k0 = ch * BKG;
        #pragma unroll
        for (int l = 0; l < 8; l++) {
            const int o = l * GEMM_THREADS + tid;
            const int r = (o >> 3) & 127;
            const int c = (o & 7) * 8;
            if (o < 1024)
                cp16(sbase + (uint32_t)(r * LDG_ + c) * 2,
                     Asrc + (size_t)r * CC + k0 + c);
            else
                cp16(sbase + (uint32_t)(TILEA + r * LDG_ + c) * 2,
                     Bsrc + (size_t)r * CC + k0 + c);
        }
    };

    issue_chunk(0, 0); CP_COMMIT();
    issue_chunk(1, 1); CP_COMMIT();

    int st_cur = 0, st_pf = 2;
    for (int ch = 0; ch < NCH; ch++) {
        CP_WAIT(1);
        __syncthreads();
        if (ch + 2 < NCH) issue_chunk(st_pf, ch + 2);
        CP_COMMIT();

        const uint32_t buf = smb + (uint32_t)st_cur * (STAGEG * 2);
        if (++st_cur == NSTG) st_cur = 0;
        if (++st_pf == NSTG) st_pf = 0;

        #pragma unroll
        for (int kk = 0; kk < BKG; kk += 16) {
            uint32_t aH[2][4], bH[4][4];
            #pragma unroll
            for (int mi = 0; mi < 2; mi++) {
                const int m = wm + mi * 16 + a_m;
                ldsm_x4(aH[mi][0], aH[mi][1], aH[mi][2], aH[mi][3],
                        buf + (uint32_t)(m * LDG_ + kk + a_k) * 2);
            }
            #pragma unroll
            for (int ni = 0; ni < 4; ni++) {
                const int n = wn + ni * 16 + b_n;
                ldsm_x4(bH[ni][0], bH[ni][1], bH[ni][2], bH[ni][3],
                        buf + (uint32_t)(TILEA + n * LDG_ + kk + b_k) * 2);
            }
            #pragma unroll
            for (int mi = 0; mi < 2; mi++)
                #pragma unroll
                for (int nj = 0; nj < 8; nj++) {
                    uint32_t bh[2] = { bH[nj >> 1][(nj & 1) * 2], bH[nj >> 1][(nj & 1) * 2 + 1] };
                    mma_f16(acc[mi][nj], aH[mi], bh);
                }
        }
    }

    if (MODE == 0) {
        const int which = n0 >> 10;
        __half* dst = (which == 0) ? g_Qh : ((which == 1) ? g_Kh : g_Vh);
        const float scl = (which == 0) ? (0.125f * LOG2E) : 1.0f;
        #pragma unroll
        for (int mi = 0; mi < 2; mi++)
            #pragma unroll
            for (int nj = 0; nj < 8; nj++) {
                const int row0 = m0 + wm + mi * 16 + (lane >> 2);
                const int col  = n0 + wn + nj * 8 + (lane & 3) * 2;
                const int o = col & 1023, hd = o >> 6, d = o & 63;
                #pragma unroll
                for (int h = 0; h < 2; h++) {
                    const int row = row0 + h * 8;
                    const int b = row >> 11, t = row & 2047;
                    const size_t off = ((size_t)(b * HH + hd) * TT + t) * DD + d;
                    *(uint32_t*)(dst + off) =
                        packf2(acc[mi][nj][h*2] * scl, acc[mi][nj][h*2+1] * scl);
                }
            }
    } else {
        #pragma unroll
        for (int mi = 0; mi < 2; mi++)
            #pragma unroll
            for (int nj = 0; nj < 8; nj++) {
                const int row0 = m0 + wm + mi * 16 + (lane >> 2);
                const int col  = n0 + wn + nj * 8 + (lane & 3) * 2;
                #pragma unroll
                for (int h = 0; h < 2; h++) {
                    const int row = row0 + h * 8;
                    float2 v = make_float2(acc[mi][nj][h*2], acc[mi][nj][h*2+1]);
                    *(float2*)(out + (size_t)row * CC + col) = v;
                }
            }
    }
}

// ---------------------------------------------------------------------------
// fp16 tensor-core flash attention (causal), exp2 softmax, KTILE=128:
// one CP_WAIT+barrier per 128 keys (2x fewer), two 64-key compute halves.
// Q smem ALIASED into stage 2 (Q region dead after pre-loop ldmatrix; stage 2
// first written at kt=0 issue, ordered by the kt=0 __syncthreads).
// smem = 3 stages x 36864 B = 110592 -> 2 CTAs/SM.
// ---------------------------------------------------------------------------
#define AQT 128
#define AKT 128
#define ALD 72
#define AKV_TILE (AKT*ALD)                 // one array (K or V), 9216 halves
#define ASTAGE (2*AKV_TILE)                // K+V, 18432 halves = 36864 B
#define ATTN_SMEM_BYTES (3*ASTAGE*2)       // 110592 B

__global__ __launch_bounds__(256, 2) void attn_mma_kernel()
{
    extern __shared__ __half smA[];
    const int tid = threadIdx.x, lane = tid & 31, w = tid >> 5;
    const int bh = blockIdx.y;
    const int qi = gridDim.x - 1 - blockIdx.x;     // longest tiles first
    const int q0 = qi * AQT;
    const size_t base = (size_t)bh * TT * DD;
    const __half* kvsrc[2] = { g_Kh + base, g_Vh + base };
    const __half* Qsrc = g_Qh + base;

    __half* stage[3] = { smA, smA + ASTAGE, smA + 2 * ASTAGE };
    __half* Qs = stage[2];                 // aliased: Q lives in stage 2 region

    const int nk = qi + 1;                 // 128-key tiles: keys 0 .. q0+127

    // K/V loader: 128 rows x 64 halves per array; 8 cp16/thread total
    const int krow = tid >> 1;                     // 0..127
    const int kcol = (tid & 1) * 32;               // 0 or 32 (4 chunks of 8)
    auto issue_kv = [&](int st, int kt) {
        const int k0 = kt * AKT;
        #pragma unroll
        for (int t = 0; t < 2; t++) {
            __half* dst = stage[st] + t * AKV_TILE;
            #pragma unroll
            for (int c = 0; c < 4; c++)
                cp16(smem_u32(dst + krow * ALD + kcol + c * 8),
                     kvsrc[t] + (size_t)(k0 + krow) * DD + kcol + c * 8);
        }
    };

    issue_kv(0, 0); CP_COMMIT();
    if (nk > 1) { issue_kv(1, 1); CP_COMMIT(); } else { CP_COMMIT(); }

    // Q tile -> smem (stage 2 region), then to registers
    #pragma unroll
    for (int l = 0; l < 4; l++) {
        int idx = l * 256 + tid;
        int r = idx >> 3, d0 = (idx & 7) * 8;
        *(uint4*)&Qs[r * ALD + d0] = *(const uint4*)(Qsrc + (size_t)(q0 + r) * DD + d0);
    }
    __syncthreads();

    const int a_m = ((lane >> 3) & 1) * 8 + (lane & 7);
    const int a_k = (lane >> 4) * 8;
    const int b_n = (lane >> 4) * 8 + (lane & 7);
    const int b_k = ((lane >> 3) & 1) * 8;
    const int t_r = ((lane >> 3) & 1) * 8 + (lane & 7);
    const int t_c = (lane >> 4) * 8;

    uint32_t qh[4][4];
    #pragma unroll
    for (int ks = 0; ks < 4; ks++) {
        uint32_t qa = smem_u32(&Qs[(w * 16 + a_m) * ALD + ks * 16 + a_k]);
        ldsm_x4(qh[ks][0], qh[ks][1], qh[ks][2], qh[ks][3], qa);
    }
    // NOTE: no extra barrier needed — the kt=0 __syncthreads below orders all
    // warps' Q reads before any warp issues the stage-2 overwrite (kt+2==2).

    float oacc[8][4];
    #pragma unroll
    for (int i = 0; i < 8; i++)
        #pragma unroll
        for (int j = 0; j < 4; j++) oacc[i][j] = 0.0f;
    float mrun[2] = { -1e30f, -1e30f }, lsum[2] = { 0.0f, 0.0f };

    const int qrow = q0 + w * 16 + (lane >> 2);

    int st_cur = 0, st_pf = 2;
    for (int kt = 0; kt < nk; kt++) {
        CP_WAIT(1);
        __syncthreads();
        if (kt + 2 < nk) issue_kv(st_pf, kt + 2);
        CP_COMMIT();

        const __half* Kst = stage[st_cur];
        const __half* Vst = stage[st_cur] + AKV_TILE;
        if (++st_cur == 3) st_cur = 0;
        if (++st_pf == 3) st_pf = 0;

        #pragma unroll
        for (int hfi = 0; hfi < 2; hfi++) {
            const int k0 = kt * AKT + hfi * 64;
            const __half* Khs = Kst + hfi * 64 * ALD;
            const __half* Vhs = Vst + hfi * 64 * ALD;

            // ---- S = Q K^T (Q carries 0.125*log2e) ----
            float sacc[8][4];
            #pragma unroll
            for (int i = 0; i < 8; i++)
                #pragma unroll
                for (int j = 0; j < 4; j++) sacc[i][j] = 0.0f;

            #pragma unroll
            for (int nbp = 0; nbp < 4; nbp++) {
                #pragma unroll
                for (int ks = 0; ks < 4; ks++) {
                    uint32_t kh4[4];
                    uint32_t ka = smem_u32(Khs + (nbp * 16 + b_n) * ALD + ks * 16 + b_k);
                    ldsm_x4(kh4[0], kh4[1], kh4[2], kh4[3], ka);
                    #pragma unroll
                    for (int hf = 0; hf < 2; hf++) {
                        const int nb = nbp * 2 + hf;
                        uint32_t bh2[2] = { kh4[hf*2], kh4[hf*2+1] };
                        mma_f16(sacc[nb], qh[ks], bh2);
                    }
                }
            }

            // ---- causal mask (only near diagonal) ----
            if (k0 + 63 > qrow) {
                #pragma unroll
                for (int nb = 0; nb < 8; nb++)
                    #pragma unroll
                    for (int c = 0; c < 4; c++) {
                        const int kg = k0 + nb * 8 + (lane & 3) * 2 + (c & 1);
                        const int qg = qrow + ((c >= 2) ? 8 : 0);
                        if (kg > qg) sacc[nb][c] = -1e30f;
                    }
            }

            // ---- online softmax (base-2) ----
            #pragma unroll
            for (int r = 0; r < 2; r++) {
                float tm = -1e30f;
                #pragma unroll
                for (int nb = 0; nb < 8; nb++)
                    tm = fmaxf(tm, fmaxf(sacc[nb][2*r], sacc[nb][2*r+1]));
                tm = fmaxf(tm, __shfl_xor_sync(0xffffffffu, tm, 1));
                tm = fmaxf(tm, __shfl_xor_sync(0xffffffffu, tm, 2));
                const float mn = fmaxf(mrun[r], tm);
                const float al = exp2f(mrun[r] - mn);
                mrun[r] = mn;
                float rs = 0.0f;
                #pragma unroll
                for (int nb = 0; nb < 8; nb++) {
                    float p0 = exp2f(sacc[nb][2*r]   - mn);
                    float p1 = exp2f(sacc[nb][2*r+1] - mn);
                    sacc[nb][2*r] = p0; sacc[nb][2*r+1] = p1;
                    rs += p0 + p1;
                }
                rs += __shfl_xor_sync(0xffffffffu, rs, 1);
                rs += __shfl_xor_sync(0xffffffffu, rs, 2);
                lsum[r] = lsum[r] * al + rs;
                #pragma unroll
                for (int dn = 0; dn < 8; dn++) {
                    oacc[dn][2*r] *= al; oacc[dn][2*r+1] *= al;
                }
            }

            // ---- O += P V (trans-ldmatrix V) ----
            #pragma unroll
            for (int j = 0; j < 4; j++) {
                uint32_t ah[4];
                ah[0] = packf2(sacc[2*j][0],   sacc[2*j][1]);
                ah[1] = packf2(sacc[2*j][2],   sacc[2*j][3]);
                ah[2] = packf2(sacc[2*j+1][0], sacc[2*j+1][1]);
                ah[3] = packf2(sacc[2*j+1][2], sacc[2*j+1][3]);
                #pragma unroll
                for (int dnp = 0; dnp < 4; dnp++) {
                    uint32_t vh4[4];
                    uint32_t va = smem_u32(Vhs + (j * 16 + t_r) * ALD + dnp * 16 + t_c);
                    ldsm_x4_t(vh4[0], vh4[1], vh4[2], vh4[3], va);
                    #pragma unroll
                    for (int hf = 0; hf < 2; hf++) {
                        const int dn = dnp * 2 + hf;
                        uint32_t bh2[2] = { vh4[hf*2], vh4[hf*2+1] };
                        mma_f16(oacc[dn], ah, bh2);
                    }
                }
            }
        }
    }

    // ---- epilogue: normalize, write fp16 O in [B*T, C] ----
    const int b = bh >> 4, h = bh & 15;
    #pragma unroll
    for (int r = 0; r < 2; r++) {
        const float inv = 1.0f / lsum[r];
        const int row = q0 + w * 16 + (lane >> 2) + r * 8;
        const size_t off = (size_t)(b * TT + row) * CC + h * DD;
        #pragma unroll
        for (int dn = 0; dn < 8; dn++) {
            const int col = dn * 8 + (lane & 3) * 2;
            *(uint32_t*)(g_Oh + off + col) =
                packf2(oacc[dn][2*r] * inv, oacc[dn][2*r+1] * inv);
        }
    }
}

// ---------------------------------------------------------------------------
extern "C" void kernel_launch(void* const* d_in, const int* in_sizes, int n_in,
                              void* d_out, int out_size)
{
    const float* x     = (const float*)d_in[0];
    const float* wqkv  = (const float*)d_in[1];
    const float* wproj = (const float*)d_in[2];
    float* out = (float*)d_out;

    cudaFuncSetAttribute((const void*)attn_mma_kernel,
                         cudaFuncAttributeMaxDynamicSharedMemorySize, ATTN_SMEM_BYTES);
    cudaFuncSetAttribute((const void*)mma_gemm_kernel<0>,
                         cudaFuncAttributeMaxDynamicSharedMemorySize, GEMM_SMEM_BYTES);
    cudaFuncSetAttribute((const void*)mma_gemm_kernel<1>,
                         cudaFuncAttributeMaxDynamicSharedMemorySize, GEMM_SMEM_BYTES);

    __half *xh, *wqh, *wph, *oh;
    cudaGetSymbolAddress((void**)&xh,  g_Xh);
    cudaGetSymbolAddress((void**)&wqh, g_Wqh);
    cudaGetSymbolAddress((void**)&wph, g_Wph);
    cudaGetSymbolAddress((void**)&oh,  g_Oh);

    convert_all_kernel<<<(N4_ALL + 255)/256, 256>>>(x, wqkv, wproj);

    mma_gemm_kernel<0><<<dim3(NQKV/128, MM/128), GEMM_THREADS, GEMM_SMEM_BYTES>>>(
        xh, wqh, nullptr);

    attn_mma_kernel<<<dim3(TT/AQT, BB*HH), 256, ATTN_SMEM_BYTES>>>();

    mma_gemm_kernel<1><<<dim3(CC/128, MM/128), GEMM_THREADS, GEMM_SMEM_BYTES>>>(
        oh, wph, out);
}

// round 15
// speedup vs baseline: 1.0646x; 1.0646x over previous
#include <cuda_runtime.h>
#include <cuda_fp16.h>
#include <cstdint>
#include <math.h>

// Problem constants
#define BB 4
#define TT 2048
#define CC 1024
#define HH 16
#define DD 64
#define MM (BB*TT)          // 8192
#define NQKV (3*CC)         // 3072

// ---------------------------------------------------------------------------
// Scratch (__device__ globals; no allocation allowed)
// ---------------------------------------------------------------------------
__device__ __half g_Qh[BB*HH*TT*DD];          // fp16, pre-scaled by 0.125*log2(e)
__device__ __half g_Kh[BB*HH*TT*DD];
__device__ __half g_Vh[BB*HH*TT*DD];
__device__ __half g_Xh[MM*CC];                // x as fp16
__device__ __half g_Wqh[NQKV*CC];             // w_qkv fp16
__device__ __half g_Wph[CC*CC];               // w_proj fp16
__device__ __half g_Oh[MM*CC];                // attn out fp16, [B*T, C]

// ---------------------------------------------------------------------------
// helpers
// ---------------------------------------------------------------------------
__device__ __forceinline__ uint32_t smem_u32(const void* p) {
    uint32_t a;
    asm("{ .reg .u64 t; cvta.to.shared.u64 t, %1; cvt.u32.u64 %0, t; }" : "=r"(a) : "l"(p));
    return a;
}
__device__ __forceinline__ void ldsm_x4(uint32_t& r0, uint32_t& r1, uint32_t& r2,
                                        uint32_t& r3, uint32_t addr) {
    asm volatile("ldmatrix.sync.aligned.m8n8.x4.shared.b16 {%0,%1,%2,%3}, [%4];"
                 : "=r"(r0), "=r"(r1), "=r"(r2), "=r"(r3) : "r"(addr));
}
__device__ __forceinline__ void ldsm_x4_t(uint32_t& r0, uint32_t& r1, uint32_t& r2,
                                          uint32_t& r3, uint32_t addr) {
    asm volatile("ldmatrix.sync.aligned.m8n8.x4.trans.shared.b16 {%0,%1,%2,%3}, [%4];"
                 : "=r"(r0), "=r"(r1), "=r"(r2), "=r"(r3) : "r"(addr));
}
__device__ __forceinline__ void mma_f16(float* c, const uint32_t* a, const uint32_t* b) {
    asm volatile("mma.sync.aligned.m16n8k16.row.col.f32.f16.f16.f32 "
                 "{%0,%1,%2,%3}, {%4,%5,%6,%7}, {%8,%9}, {%0,%1,%2,%3};"
                 : "+f"(c[0]), "+f"(c[1]), "+f"(c[2]), "+f"(c[3])
                 : "r"(a[0]), "r"(a[1]), "r"(a[2]), "r"(a[3]), "r"(b[0]), "r"(b[1]));
}
__device__ __forceinline__ void cp16(uint32_t dst, const void* src) {
    asm volatile("cp.async.cg.shared.global [%0], [%1], 16;" :: "r"(dst), "l"(src));
}
#define CP_COMMIT() asm volatile("cp.async.commit_group;" ::: "memory")
#define CP_WAIT(N)  asm volatile("cp.async.wait_group %0;" :: "n"(N) : "memory")

__device__ __forceinline__ uint32_t packf2(float x, float y) {
    __half2 t = __floats2half2_rn(x, y);   // x -> low half
    return *reinterpret_cast<uint32_t*>(&t);
}

// ---------------------------------------------------------------------------
// fused fp32 -> fp16 conversion (x, w_qkv, w_proj in one launch)
// ---------------------------------------------------------------------------
#define N4_X    (MM*CC/4)      // 2097152
#define N4_WQ   (NQKV*CC/4)    //  786432
#define N4_WP   (CC*CC/4)      //  262144
#define N4_ALL  (N4_X + N4_WQ + N4_WP)

__global__ __launch_bounds__(256) void convert_all_kernel(
    const float* __restrict__ x, const float* __restrict__ wq,
    const float* __restrict__ wp)
{
    int i = blockIdx.x * blockDim.x + threadIdx.x;
    if (i >= N4_ALL) return;
    const float* src; __half* dst; int j;
    if (i < N4_X)               { src = x;  dst = g_Xh;  j = i; }
    else if (i < N4_X + N4_WQ)  { src = wq; dst = g_Wqh; j = i - N4_X; }
    else                        { src = wp; dst = g_Wph; j = i - N4_X - N4_WQ; }
    float4 v = ((const float4*)src)[j];
    uint2 o;
    o.x = packf2(v.x, v.y);
    o.y = packf2(v.z, v.w);
    ((uint2*)dst)[j] = o;
}

// ---------------------------------------------------------------------------
// HMMA fp16 single-pass GEMM (unchanged from R13): C = Ah*Bh
// 256 threads / 8 warps, warp 32x64, CTA 128x128, BK=64, 3-stage, 2 CTA/SM.
// MODE 0: Q -> fp16 scaled 0.125*log2e, K/V fp16, [B,H,T,D]. MODE 1: fp32 out.
// ---------------------------------------------------------------------------
#define BKG 64
#define LDG_ 72
#define TILEA (128*LDG_)
#define TILEB (128*LDG_)
#define STAGEG (TILEA + TILEB)            // 18432 halves
#define NSTG 3
#define GEMM_SMEM_BYTES (NSTG*STAGEG*2)   // 110592 B
#define GEMM_THREADS 256
#define LOG2E 1.44269504088896f

template<int MODE>
__global__ __launch_bounds__(GEMM_THREADS, 2) void mma_gemm_kernel(
    const __half* __restrict__ Ah, const __half* __restrict__ Bh,
    float* __restrict__ out)
{
    extern __shared__ __half sm[];
    const uint32_t smb = smem_u32(sm);
    const int tid = threadIdx.x;
    const int lane = tid & 31, wid = tid >> 5;
    const int wm = (wid >> 1) * 32;
    const int wn = (wid & 1) * 64;
    const int n0 = blockIdx.x * 128;
    const int m0 = blockIdx.y * 128;

    const __half* Asrc = Ah + (size_t)m0 * CC;
    const __half* Bsrc = Bh + (size_t)n0 * CC;

    const int NCH = CC / BKG;   // 16

    float acc[2][8][4];
    #pragma unroll
    for (int a = 0; a < 2; a++)
        #pragma unroll
        for (int b = 0; b < 8; b++)
            #pragma unroll
            for (int c = 0; c < 4; c++) acc[a][b][c] = 0.0f;

    const int a_m = ((lane >> 3) & 1) * 8 + (lane & 7);
    const int a_k = (lane >> 4) * 8;
    const int b_n = (lane >> 4) * 8 + (lane & 7);
    const int b_k = ((lane >> 3) & 1) * 8;

    auto issue_chunk = [&](int st, int ch) {
        const uint32_t sbase = smb + (uint32_t)st * (STAGEG * 2);
        const int k0 = ch * BKG;
        #pragma unroll
        for (int l = 0; l < 8; l++) {
            const int o = l * GEMM_THREADS + tid;
            const int r = (o >> 3) & 127;
            const int c = (o & 7) * 8;
            if (o < 1024)
                cp16(sbase + (uint32_t)(r * LDG_ + c) * 2,
                     Asrc + (size_t)r * CC + k0 + c);
            else
                cp16(sbase + (uint32_t)(TILEA + r * LDG_ + c) * 2,
                     Bsrc + (size_t)r * CC + k0 + c);
        }
    };

    issue_chunk(0, 0); CP_COMMIT();
    issue_chunk(1, 1); CP_COMMIT();

    int st_cur = 0, st_pf = 2;
    for (int ch = 0; ch < NCH; ch++) {
        CP_WAIT(1);
        __syncthreads();
        if (ch + 2 < NCH) issue_chunk(st_pf, ch + 2);
        CP_COMMIT();

        const uint32_t buf = smb + (uint32_t)st_cur * (STAGEG * 2);
        if (++st_cur == NSTG) st_cur = 0;
        if (++st_pf == NSTG) st_pf = 0;

        #pragma unroll
        for (int kk = 0; kk < BKG; kk += 16) {
            uint32_t aH[2][4], bH[4][4];
            #pragma unroll
            for (int mi = 0; mi < 2; mi++) {
                const int m = wm + mi * 16 + a_m;
                ldsm_x4(aH[mi][0], aH[mi][1], aH[mi][2], aH[mi][3],
                        buf + (uint32_t)(m * LDG_ + kk + a_k) * 2);
            }
            #pragma unroll
            for (int ni = 0; ni < 4; ni++) {
                const int n = wn + ni * 16 + b_n;
                ldsm_x4(bH[ni][0], bH[ni][1], bH[ni][2], bH[ni][3],
                        buf + (uint32_t)(TILEA + n * LDG_ + kk + b_k) * 2);
            }
            #pragma unroll
            for (int mi = 0; mi < 2; mi++)
                #pragma unroll
                for (int nj = 0; nj < 8; nj++) {
                    uint32_t bh[2] = { bH[nj >> 1][(nj & 1) * 2], bH[nj >> 1][(nj & 1) * 2 + 1] };
                    mma_f16(acc[mi][nj], aH[mi], bh);
                }
        }
    }

    if (MODE == 0) {
        const int which = n0 >> 10;
        __half* dst = (which == 0) ? g_Qh : ((which == 1) ? g_Kh : g_Vh);
        const float scl = (which == 0) ? (0.125f * LOG2E) : 1.0f;
        #pragma unroll
        for (int mi = 0; mi < 2; mi++)
            #pragma unroll
            for (int nj = 0; nj < 8; nj++) {
                const int row0 = m0 + wm + mi * 16 + (lane >> 2);
                const int col  = n0 + wn + nj * 8 + (lane & 3) * 2;
                const int o = col & 1023, hd = o >> 6, d = o & 63;
                #pragma unroll
                for (int h = 0; h < 2; h++) {
                    const int row = row0 + h * 8;
                    const int b = row >> 11, t = row & 2047;
                    const size_t off = ((size_t)(b * HH + hd) * TT + t) * DD + d;
                    *(uint32_t*)(dst + off) =
                        packf2(acc[mi][nj][h*2] * scl, acc[mi][nj][h*2+1] * scl);
                }
            }
    } else {
        #pragma unroll
        for (int mi = 0; mi < 2; mi++)
            #pragma unroll
            for (int nj = 0; nj < 8; nj++) {
                const int row0 = m0 + wm + mi * 16 + (lane >> 2);
                const int col  = n0 + wn + nj * 8 + (lane & 3) * 2;
                #pragma unroll
                for (int h = 0; h < 2; h++) {
                    const int row = row0 + h * 8;
                    float2 v = make_float2(acc[mi][nj][h*2], acc[mi][nj][h*2+1]);
                    *(float2*)(out + (size_t)row * CC + col) = v;
                }
            }
    }
}

// ---------------------------------------------------------------------------
// fp16 single-pass tensor-core flash attention (causal), exp2 softmax,
// KTILE=64 (reverted), 4-stage cp.async KV ring with CP_WAIT(2)
// (prefetch distance 3 tiles). smem = Q 18.4KB + 4x18.4KB = 92.2KB -> 2 CTA/SM.
// ---------------------------------------------------------------------------
#define AQT 128
#define AKT 64
#define ALD 72
#define ANST 4

struct AttnSmem {
    __half Q[AQT*ALD];
    __half KV[ANST][2][AKT*ALD];       // stage, {Kh,Vh}
};
#define ATTN_SMEM_BYTES ((int)sizeof(AttnSmem))   // 92160

__global__ __launch_bounds__(256, 2) void attn_mma_kernel()
{
    extern __shared__ char smraw[];
    AttnSmem& s = *(AttnSmem*)smraw;

    const int tid = threadIdx.x, lane = tid & 31, w = tid >> 5;
    const int bh = blockIdx.y;
    const int qi = gridDim.x - 1 - blockIdx.x;     // longest tiles first
    const int q0 = qi * AQT;
    const size_t base = (size_t)bh * TT * DD;
    const __half* kvsrc[2] = { g_Kh + base, g_Vh + base };
    const __half* Qsrc = g_Qh + base;

    const int nk = 2 * qi + 2;

    const int kr0 = tid >> 3, kr1 = 32 + (tid >> 3);
    const int kc = (tid & 7) * 8;

    auto issue_kv = [&](int st, int kt) {
        const int k0 = kt * AKT;
        #pragma unroll
        for (int t = 0; t < 2; t++) {
            cp16(smem_u32(&s.KV[st][t][kr0 * ALD + kc]),
                 kvsrc[t] + (size_t)(k0 + kr0) * DD + kc);
            cp16(smem_u32(&s.KV[st][t][kr1 * ALD + kc]),
                 kvsrc[t] + (size_t)(k0 + kr1) * DD + kc);
        }
    };

    // prologue: prefetch up to 3 tiles (nk >= 2 always)
    issue_kv(0, 0); CP_COMMIT();
    issue_kv(1, 1); CP_COMMIT();
    if (2 < nk) issue_kv(2, 2);
    CP_COMMIT();

    #pragma unroll
    for (int l = 0; l < 4; l++) {
        int idx = l * 256 + tid;
        int r = idx >> 3, d0 = (idx & 7) * 8;
        *(uint4*)&s.Q[r * ALD + d0] = *(const uint4*)(Qsrc + (size_t)(q0 + r) * DD + d0);
    }
    __syncthreads();

    const int a_m = ((lane >> 3) & 1) * 8 + (lane & 7);
    const int a_k = (lane >> 4) * 8;
    const int b_n = (lane >> 4) * 8 + (lane & 7);
    const int b_k = ((lane >> 3) & 1) * 8;
    const int t_r = ((lane >> 3) & 1) * 8 + (lane & 7);
    const int t_c = (lane >> 4) * 8;

    uint32_t qh[4][4];
    #pragma unroll
    for (int ks = 0; ks < 4; ks++) {
        uint32_t qa = smem_u32(&s.Q[(w * 16 + a_m) * ALD + ks * 16 + a_k]);
        ldsm_x4(qh[ks][0], qh[ks][1], qh[ks][2], qh[ks][3], qa);
    }

    float oacc[8][4];
    #pragma unroll
    for (int i = 0; i < 8; i++)
        #pragma unroll
        for (int j = 0; j < 4; j++) oacc[i][j] = 0.0f;
    float mrun[2] = { -1e30f, -1e30f }, lsum[2] = { 0.0f, 0.0f };

    const int qrow = q0 + w * 16 + (lane >> 2);

    int st_cur = 0, st_pf = 3;
    for (int kt = 0; kt < nk; kt++) {
        const int k0 = kt * AKT;
        CP_WAIT(2);
        __syncthreads();
        if (kt + 3 < nk) issue_kv(st_pf, kt + 3);
        CP_COMMIT();

        const __half* Khs = s.KV[st_cur][0];
        const __half* Vhs = s.KV[st_cur][1];
        if (++st_cur == ANST) st_cur = 0;
        if (++st_pf == ANST) st_pf = 0;

        // ---- S = Q K^T  (Q carries 0.125*log2e) ----
        float sacc[8][4];
        #pragma unroll
        for (int i = 0; i < 8; i++)
            #pragma unroll
            for (int j = 0; j < 4; j++) sacc[i][j] = 0.0f;

        #pragma unroll
        for (int nbp = 0; nbp < 4; nbp++) {
            #pragma unroll
            for (int ks = 0; ks < 4; ks++) {
                uint32_t kh4[4];
                uint32_t ka = smem_u32(Khs + (nbp * 16 + b_n) * ALD + ks * 16 + b_k);
                ldsm_x4(kh4[0], kh4[1], kh4[2], kh4[3], ka);
                #pragma unroll
                for (int hf = 0; hf < 2; hf++) {
                    const int nb = nbp * 2 + hf;
                    uint32_t bh2[2] = { kh4[hf*2], kh4[hf*2+1] };
                    mma_f16(sacc[nb], qh[ks], bh2);
                }
            }
        }

        // ---- causal mask ----
        if (k0 + 63 > qrow) {
            #pragma unroll
            for (int nb = 0; nb < 8; nb++)
                #pragma unroll
                for (int c = 0; c < 4; c++) {
                    const int kg = k0 + nb * 8 + (lane & 3) * 2 + (c & 1);
                    const int qg = qrow + ((c >= 2) ? 8 : 0);
                    if (kg > qg) sacc[nb][c] = -1e30f;
                }
        }

        // ---- online softmax (base-2) ----
        #pragma unroll
        for (int r = 0; r < 2; r++) {
            float tm = -1e30f;
            #pragma unroll
            for (int nb = 0; nb < 8; nb++)
                tm = fmaxf(tm, fmaxf(sacc[nb][2*r], sacc[nb][2*r+1]));
            tm = fmaxf(tm, __shfl_xor_sync(0xffffffffu, tm, 1));
            tm = fmaxf(tm, __shfl_xor_sync(0xffffffffu, tm, 2));
            const float mn = fmaxf(mrun[r], tm);
            const float al = exp2f(mrun[r] - mn);
            mrun[r] = mn;
            float rs = 0.0f;
            #pragma unroll
            for (int nb = 0; nb < 8; nb++) {
                float p0 = exp2f(sacc[nb][2*r]   - mn);
                float p1 = exp2f(sacc[nb][2*r+1] - mn);
                sacc[nb][2*r] = p0; sacc[nb][2*r+1] = p1;
                rs += p0 + p1;
            }
            rs += __shfl_xor_sync(0xffffffffu, rs, 1);
            rs += __shfl_xor_sync(0xffffffffu, rs, 2);
            lsum[r] = lsum[r] * al + rs;
            #pragma unroll
            for (int dn = 0; dn < 8; dn++) {
                oacc[dn][2*r] *= al; oacc[dn][2*r+1] *= al;
            }
        }

        // ---- O += P V (trans-ldmatrix V) ----
        #pragma unroll
        for (int j = 0; j < 4; j++) {
            uint32_t ah[4];
            ah[0] = packf2(sacc[2*j][0],   sacc[2*j][1]);
            ah[1] = packf2(sacc[2*j][2],   sacc[2*j][3]);
            ah[2] = packf2(sacc[2*j+1][0], sacc[2*j+1][1]);
            ah[3] = packf2(sacc[2*j+1][2], sacc[2*j+1][3]);
            #pragma unroll
            for (int dnp = 0; dnp < 4; dnp++) {
                uint32_t vh4[4];
                uint32_t va = smem_u32(Vhs + (j * 16 + t_r) * ALD + dnp * 16 + t_c);
                ldsm_x4_t(vh4[0], vh4[1], vh4[2], vh4[3], va);
                #pragma unroll
                for (int hf = 0; hf < 2; hf++) {
                    const int dn = dnp * 2 + hf;
                    uint32_t bh2[2] = { vh4[hf*2], vh4[hf*2+1] };
                    mma_f16(oacc[dn], ah, bh2);
                }
            }
        }
    }

    // ---- epilogue: normalize, write fp16 O in [B*T, C] ----
    const int b = bh >> 4, h = bh & 15;
    #pragma unroll
    for (int r = 0; r < 2; r++) {
        const float inv = 1.0f / lsum[r];
        const int row = q0 + w * 16 + (lane >> 2) + r * 8;
        const size_t off = (size_t)(b * TT + row) * CC + h * DD;
        #pragma unroll
        for (int dn = 0; dn < 8; dn++) {
            const int col = dn * 8 + (lane & 3) * 2;
            *(uint32_t*)(g_Oh + off + col) =
                packf2(oacc[dn][2*r] * inv, oacc[dn][2*r+1] * inv);
        }
    }
}

// ---------------------------------------------------------------------------
extern "C" void kernel_launch(void* const* d_in, const int* in_sizes, int n_in,
                              void* d_out, int out_size)
{
    const float* x     = (const float*)d_in[0];
    const float* wqkv  = (const float*)d_in[1];
    const float* wproj = (const float*)d_in[2];
    float* out = (float*)d_out;

    cudaFuncSetAttribute((const void*)attn_mma_kernel,
                         cudaFuncAttributeMaxDynamicSharedMemorySize, ATTN_SMEM_BYTES);
    cudaFuncSetAttribute((const void*)mma_gemm_kernel<0>,
                         cudaFuncAttributeMaxDynamicSharedMemorySize, GEMM_SMEM_BYTES);
    cudaFuncSetAttribute((const void*)mma_gemm_kernel<1>,
                         cudaFuncAttributeMaxDynamicSharedMemorySize, GEMM_SMEM_BYTES);

    __half *xh, *wqh, *wph, *oh;
    cudaGetSymbolAddress((void**)&xh,  g_Xh);
    cudaGetSymbolAddress((void**)&wqh, g_Wqh);
    cudaGetSymbolAddress((void**)&wph, g_Wph);
    cudaGetSymbolAddress((void**)&oh,  g_Oh);

    convert_all_kernel<<<(N4_ALL + 255)/256, 256>>>(x, wqkv, wproj);

    mma_gemm_kernel<0><<<dim3(NQKV/128, MM/128), GEMM_THREADS, GEMM_SMEM_BYTES>>>(
        xh, wqh, nullptr);

    attn_mma_kernel<<<dim3(TT/AQT, BB*HH), 256, ATTN_SMEM_BYTES>>>();

    mma_gemm_kernel<1><<<dim3(CC/128, MM/128), GEMM_THREADS, GEMM_SMEM_BYTES>>>(
        oh, wph, out);
}

// round 16
// speedup vs baseline: 1.1693x; 1.0984x over previous
#include <cuda_runtime.h>
#include <cuda_fp16.h>
#include <cstdint>
#include <math.h>

// Problem constants
#define BB 4
#define TT 2048
#define CC 1024
#define HH 16
#define DD 64
#define MM (BB*TT)          // 8192
#define NQKV (3*CC)         // 3072

// ---------------------------------------------------------------------------
// Scratch (__device__ globals; no allocation allowed)
// ---------------------------------------------------------------------------
__device__ __half g_Qh[BB*HH*TT*DD];          // fp16, pre-scaled by 0.125*log2(e)
__device__ __half g_Kh[BB*HH*TT*DD];
__device__ __half g_Vh[BB*HH*TT*DD];
__device__ __half g_Xh[MM*CC];                // x as fp16
__device__ __half g_Wqh[NQKV*CC];             // w_qkv fp16
__device__ __half g_Wph[CC*CC];               // w_proj fp16
__device__ __half g_Oh[MM*CC];                // attn out fp16, [B*T, C]

// ---------------------------------------------------------------------------
// helpers
// ---------------------------------------------------------------------------
__device__ __forceinline__ uint32_t smem_u32(const void* p) {
    uint32_t a;
    asm("{ .reg .u64 t; cvta.to.shared.u64 t, %1; cvt.u32.u64 %0, t; }" : "=r"(a) : "l"(p));
    return a;
}
__device__ __forceinline__ void ldsm_x4(uint32_t& r0, uint32_t& r1, uint32_t& r2,
                                        uint32_t& r3, uint32_t addr) {
    asm volatile("ldmatrix.sync.aligned.m8n8.x4.shared.b16 {%0,%1,%2,%3}, [%4];"
                 : "=r"(r0), "=r"(r1), "=r"(r2), "=r"(r3) : "r"(addr));
}
__device__ __forceinline__ void ldsm_x4_t(uint32_t& r0, uint32_t& r1, uint32_t& r2,
                                          uint32_t& r3, uint32_t addr) {
    asm volatile("ldmatrix.sync.aligned.m8n8.x4.trans.shared.b16 {%0,%1,%2,%3}, [%4];"
                 : "=r"(r0), "=r"(r1), "=r"(r2), "=r"(r3) : "r"(addr));
}
__device__ __forceinline__ void mma_f16(float* c, const uint32_t* a, const uint32_t* b) {
    asm volatile("mma.sync.aligned.m16n8k16.row.col.f32.f16.f16.f32 "
                 "{%0,%1,%2,%3}, {%4,%5,%6,%7}, {%8,%9}, {%0,%1,%2,%3};"
                 : "+f"(c[0]), "+f"(c[1]), "+f"(c[2]), "+f"(c[3])
                 : "r"(a[0]), "r"(a[1]), "r"(a[2]), "r"(a[3]), "r"(b[0]), "r"(b[1]));
}
__device__ __forceinline__ void cp16(uint32_t dst, const void* src) {
    asm volatile("cp.async.cg.shared.global [%0], [%1], 16;" :: "r"(dst), "l"(src));
}
#define CP_COMMIT() asm volatile("cp.async.commit_group;" ::: "memory")
#define CP_WAIT(N)  asm volatile("cp.async.wait_group %0;" :: "n"(N) : "memory")

__device__ __forceinline__ uint32_t packf2(float x, float y) {
    __half2 t = __floats2half2_rn(x, y);   // x -> low half
    return *reinterpret_cast<uint32_t*>(&t);
}

// ---------------------------------------------------------------------------
// fused fp32 -> fp16 conversion (x, w_qkv, w_proj in one launch)
// ---------------------------------------------------------------------------
#define N4_X    (MM*CC/4)      // 2097152
#define N4_WQ   (NQKV*CC/4)    //  786432
#define N4_WP   (CC*CC/4)      //  262144
#define N4_ALL  (N4_X + N4_WQ + N4_WP)

__global__ __launch_bounds__(256) void convert_all_kernel(
    const float* __restrict__ x, const float* __restrict__ wq,
    const float* __restrict__ wp)
{
    int i = blockIdx.x * blockDim.x + threadIdx.x;
    if (i >= N4_ALL) return;
    const float* src; __half* dst; int j;
    if (i < N4_X)               { src = x;  dst = g_Xh;  j = i; }
    else if (i < N4_X + N4_WQ)  { src = wq; dst = g_Wqh; j = i - N4_X; }
    else                        { src = wp; dst = g_Wph; j = i - N4_X - N4_WQ; }
    float4 v = ((const float4*)src)[j];
    uint2 o;
    o.x = packf2(v.x, v.y);
    o.y = packf2(v.z, v.w);
    ((uint2*)dst)[j] = o;
}

// ---------------------------------------------------------------------------
// HMMA fp16 single-pass GEMM (unchanged): C = Ah*Bh
// 256 threads / 8 warps, warp 32x64, CTA 128x128, BK=64, 3-stage, 2 CTA/SM.
// MODE 0: Q -> fp16 scaled 0.125*log2e, K/V fp16, [B,H,T,D]. MODE 1: fp32 out.
// ---------------------------------------------------------------------------
#define BKG 64
#define LDG_ 72
#define TILEA (128*LDG_)
#define TILEB (128*LDG_)
#define STAGEG (TILEA + TILEB)            // 18432 halves
#define NSTG 3
#define GEMM_SMEM_BYTES (NSTG*STAGEG*2)   // 110592 B
#define GEMM_THREADS 256
#define LOG2E 1.44269504088896f

template<int MODE>
__global__ __launch_bounds__(GEMM_THREADS, 2) void mma_gemm_kernel(
    const __half* __restrict__ Ah, const __half* __restrict__ Bh,
    float* __restrict__ out)
{
    extern __shared__ __half sm[];
    const uint32_t smb = smem_u32(sm);
    const int tid = threadIdx.x;
    const int lane = tid & 31, wid = tid >> 5;
    const int wm = (wid >> 1) * 32;
    const int wn = (wid & 1) * 64;
    const int n0 = blockIdx.x * 128;
    const int m0 = blockIdx.y * 128;

    const __half* Asrc = Ah + (size_t)m0 * CC;
    const __half* Bsrc = Bh + (size_t)n0 * CC;

    const int NCH = CC / BKG;   // 16

    float acc[2][8][4];
    #pragma unroll
    for (int a = 0; a < 2; a++)
        #pragma unroll
        for (int b = 0; b < 8; b++)
            #pragma unroll
            for (int c = 0; c < 4; c++) acc[a][b][c] = 0.0f;

    const int a_m = ((lane >> 3) & 1) * 8 + (lane & 7);
    const int a_k = (lane >> 4) * 8;
    const int b_n = (lane >> 4) * 8 + (lane & 7);
    const int b_k = ((lane >> 3) & 1) * 8;

    auto issue_chunk = [&](int st, int ch) {
        const uint32_t sbase = smb + (uint32_t)st * (STAGEG * 2);
        const int k0 = ch * BKG;
        #pragma unroll
        for (int l = 0; l < 8; l++) {
            const int o = l * GEMM_THREADS + tid;
            const int r = (o >> 3) & 127;
            const int c = (o & 7) * 8;
            if (o < 1024)
                cp16(sbase + (uint32_t)(r * LDG_ + c) * 2,
                     Asrc + (size_t)r * CC + k0 + c);
            else
                cp16(sbase + (uint32_t)(TILEA + r * LDG_ + c) * 2,
                     Bsrc + (size_t)r * CC + k0 + c);
        }
    };

    issue_chunk(0, 0); CP_COMMIT();
    issue_chunk(1, 1); CP_COMMIT();

    int st_cur = 0, st_pf = 2;
    for (int ch = 0; ch < NCH; ch++) {
        CP_WAIT(1);
        __syncthreads();
        if (ch + 2 < NCH) issue_chunk(st_pf, ch + 2);
        CP_COMMIT();

        const uint32_t buf = smb + (uint32_t)st_cur * (STAGEG * 2);
        if (++st_cur == NSTG) st_cur = 0;
        if (++st_pf == NSTG) st_pf = 0;

        #pragma unroll
        for (int kk = 0; kk < BKG; kk += 16) {
            uint32_t aH[2][4], bH[4][4];
            #pragma unroll
            for (int mi = 0; mi < 2; mi++) {
                const int m = wm + mi * 16 + a_m;
                ldsm_x4(aH[mi][0], aH[mi][1], aH[mi][2], aH[mi][3],
                        buf + (uint32_t)(m * LDG_ + kk + a_k) * 2);
            }
            #pragma unroll
            for (int ni = 0; ni < 4; ni++) {
                const int n = wn + ni * 16 + b_n;
                ldsm_x4(bH[ni][0], bH[ni][1], bH[ni][2], bH[ni][3],
                        buf + (uint32_t)(TILEA + n * LDG_ + kk + b_k) * 2);
            }
            #pragma unroll
            for (int mi = 0; mi < 2; mi++)
                #pragma unroll
                for (int nj = 0; nj < 8; nj++) {
                    uint32_t bh[2] = { bH[nj >> 1][(nj & 1) * 2], bH[nj >> 1][(nj & 1) * 2 + 1] };
                    mma_f16(acc[mi][nj], aH[mi], bh);
                }
        }
    }

    if (MODE == 0) {
        const int which = n0 >> 10;
        __half* dst = (which == 0) ? g_Qh : ((which == 1) ? g_Kh : g_Vh);
        const float scl = (which == 0) ? (0.125f * LOG2E) : 1.0f;
        #pragma unroll
        for (int mi = 0; mi < 2; mi++)
            #pragma unroll
            for (int nj = 0; nj < 8; nj++) {
                const int row0 = m0 + wm + mi * 16 + (lane >> 2);
                const int col  = n0 + wn + nj * 8 + (lane & 3) * 2;
                const int o = col & 1023, hd = o >> 6, d = o & 63;
                #pragma unroll
                for (int h = 0; h < 2; h++) {
                    const int row = row0 + h * 8;
                    const int b = row >> 11, t = row & 2047;
                    const size_t off = ((size_t)(b * HH + hd) * TT + t) * DD + d;
                    *(uint32_t*)(dst + off) =
                        packf2(acc[mi][nj][h*2] * scl, acc[mi][nj][h*2+1] * scl);
                }
            }
    } else {
        #pragma unroll
        for (int mi = 0; mi < 2; mi++)
            #pragma unroll
            for (int nj = 0; nj < 8; nj++) {
                const int row0 = m0 + wm + mi * 16 + (lane >> 2);
                const int col  = n0 + wn + nj * 8 + (lane & 3) * 2;
                #pragma unroll
                for (int h = 0; h < 2; h++) {
                    const int row = row0 + h * 8;
                    float2 v = make_float2(acc[mi][nj][h*2], acc[mi][nj][h*2+1]);
                    *(float2*)(out + (size_t)row * CC + col) = v;
                }
            }
    }
}

// ---------------------------------------------------------------------------
// fp16 single-pass tensor-core flash attention (causal), exp2 softmax,
// KTILE=64, 4-stage cp.async KV ring, CP_WAIT(2).
// NEW: 1D grid with GLOBAL longest-first ordering; fully-masked warps skip
// the per-tile compute body (provable no-op: alpha=1, rs=0, P=0).
// smem = Q 18.4KB + 4x18.4KB = 92.2KB -> 2 CTA/SM.
// ---------------------------------------------------------------------------
#define AQT 128
#define AKT 64
#define ALD 72
#define ANST 4

struct AttnSmem {
    __half Q[AQT*ALD];
    __half KV[ANST][2][AKT*ALD];       // stage, {Kh,Vh}
};
#define ATTN_SMEM_BYTES ((int)sizeof(AttnSmem))   // 92160

__global__ __launch_bounds__(256, 2) void attn_mma_kernel()
{
    extern __shared__ char smraw[];
    AttnSmem& s = *(AttnSmem*)smraw;

    const int tid = threadIdx.x, lane = tid & 31, w = tid >> 5;
    // 1D grid, global longest-first: bid 0..1023 -> qi 15..0 (outer), bh 0..63
    const int bid = blockIdx.x;
    const int qi = (TT/AQT - 1) - (bid >> 6);
    const int bh = bid & 63;
    const int q0 = qi * AQT;
    const size_t base = (size_t)bh * TT * DD;
    const __half* kvsrc[2] = { g_Kh + base, g_Vh + base };
    const __half* Qsrc = g_Qh + base;

    const int nk = 2 * qi + 2;

    const int kr0 = tid >> 3, kr1 = 32 + (tid >> 3);
    const int kc = (tid & 7) * 8;

    auto issue_kv = [&](int st, int kt) {
        const int k0 = kt * AKT;
        #pragma unroll
        for (int t = 0; t < 2; t++) {
            cp16(smem_u32(&s.KV[st][t][kr0 * ALD + kc]),
                 kvsrc[t] + (size_t)(k0 + kr0) * DD + kc);
            cp16(smem_u32(&s.KV[st][t][kr1 * ALD + kc]),
                 kvsrc[t] + (size_t)(k0 + kr1) * DD + kc);
        }
    };

    // prologue: prefetch up to 3 tiles (nk >= 2 always)
    issue_kv(0, 0); CP_COMMIT();
    issue_kv(1, 1); CP_COMMIT();
    if (2 < nk) issue_kv(2, 2);
    CP_COMMIT();

    #pragma unroll
    for (int l = 0; l < 4; l++) {
        int idx = l * 256 + tid;
        int r = idx >> 3, d0 = (idx & 7) * 8;
        *(uint4*)&s.Q[r * ALD + d0] = *(const uint4*)(Qsrc + (size_t)(q0 + r) * DD + d0);
    }
    __syncthreads();

    const int a_m = ((lane >> 3) & 1) * 8 + (lane & 7);
    const int a_k = (lane >> 4) * 8;
    const int b_n = (lane >> 4) * 8 + (lane & 7);
    const int b_k = ((lane >> 3) & 1) * 8;
    const int t_r = ((lane >> 3) & 1) * 8 + (lane & 7);
    const int t_c = (lane >> 4) * 8;

    uint32_t qh[4][4];
    #pragma unroll
    for (int ks = 0; ks < 4; ks++) {
        uint32_t qa = smem_u32(&s.Q[(w * 16 + a_m) * ALD + ks * 16 + a_k]);
        ldsm_x4(qh[ks][0], qh[ks][1], qh[ks][2], qh[ks][3], qa);
    }

    float oacc[8][4];
    #pragma unroll
    for (int i = 0; i < 8; i++)
        #pragma unroll
        for (int j = 0; j < 4; j++) oacc[i][j] = 0.0f;
    float mrun[2] = { -1e30f, -1e30f }, lsum[2] = { 0.0f, 0.0f };

    const int qrow = q0 + w * 16 + (lane >> 2);
    const int wrow_max = q0 + w * 16 + 15;     // largest q-row this warp owns

    int st_cur = 0, st_pf = 3;
    for (int kt = 0; kt < nk; kt++) {
        const int k0 = kt * AKT;
        CP_WAIT(2);
        __syncthreads();
        if (kt + 3 < nk) issue_kv(st_pf, kt + 3);
        CP_COMMIT();

        const __half* Khs = s.KV[st_cur][0];
        const __half* Vhs = s.KV[st_cur][1];
        if (++st_cur == ANST) st_cur = 0;
        if (++st_pf == ANST) st_pf = 0;

        // Fully-masked warp skip: if every key in this tile is strictly above
        // this warp's rows, softmax/PV is a provable no-op — skip the body.
        // (Warp-uniform predicate; barriers are outside this block.)
        if (k0 > wrow_max) continue;

        // ---- S = Q K^T  (Q carries 0.125*log2e) ----
        float sacc[8][4];
        #pragma unroll
        for (int i = 0; i < 8; i++)
            #pragma unroll
            for (int j = 0; j < 4; j++) sacc[i][j] = 0.0f;

        #pragma unroll
        for (int nbp = 0; nbp < 4; nbp++) {
            #pragma unroll
            for (int ks = 0; ks < 4; ks++) {
                uint32_t kh4[4];
                uint32_t ka = smem_u32(Khs + (nbp * 16 + b_n) * ALD + ks * 16 + b_k);
                ldsm_x4(kh4[0], kh4[1], kh4[2], kh4[3], ka);
                #pragma unroll
                for (int hf = 0; hf < 2; hf++) {
                    const int nb = nbp * 2 + hf;
                    uint32_t bh2[2] = { kh4[hf*2], kh4[hf*2+1] };
                    mma_f16(sacc[nb], qh[ks], bh2);
                }
            }
        }

        // ---- causal mask ----
        if (k0 + 63 > qrow) {
            #pragma unroll
            for (int nb = 0; nb < 8; nb++)
                #pragma unroll
                for (int c = 0; c < 4; c++) {
                    const int kg = k0 + nb * 8 + (lane & 3) * 2 + (c & 1);
                    const int qg = qrow + ((c >= 2) ? 8 : 0);
                    if (kg > qg) sacc[nb][c] = -1e30f;
                }
        }

        // ---- online softmax (base-2) ----
        #pragma unroll
        for (int r = 0; r < 2; r++) {
            float tm = -1e30f;
            #pragma unroll
            for (int nb = 0; nb < 8; nb++)
                tm = fmaxf(tm, fmaxf(sacc[nb][2*r], sacc[nb][2*r+1]));
            tm = fmaxf(tm, __shfl_xor_sync(0xffffffffu, tm, 1));
            tm = fmaxf(tm, __shfl_xor_sync(0xffffffffu, tm, 2));
            const float mn = fmaxf(mrun[r], tm);
            const float al = exp2f(mrun[r] - mn);
            mrun[r] = mn;
            float rs = 0.0f;
            #pragma unroll
            for (int nb = 0; nb < 8; nb++) {
                float p0 = exp2f(sacc[nb][2*r]   - mn);
                float p1 = exp2f(sacc[nb][2*r+1] - mn);
                sacc[nb][2*r] = p0; sacc[nb][2*r+1] = p1;
                rs += p0 + p1;
            }
            rs += __shfl_xor_sync(0xffffffffu, rs, 1);
            rs += __shfl_xor_sync(0xffffffffu, rs, 2);
            lsum[r] = lsum[r] * al + rs;
            #pragma unroll
            for (int dn = 0; dn < 8; dn++) {
                oacc[dn][2*r] *= al; oacc[dn][2*r+1] *= al;
            }
        }

        // ---- O += P V (trans-ldmatrix V) ----
        #pragma unroll
        for (int j = 0; j < 4; j++) {
            uint32_t ah[4];
            ah[0] = packf2(sacc[2*j][0],   sacc[2*j][1]);
            ah[1] = packf2(sacc[2*j][2],   sacc[2*j][3]);
            ah[2] = packf2(sacc[2*j+1][0], sacc[2*j+1][1]);
            ah[3] = packf2(sacc[2*j+1][2], sacc[2*j+1][3]);
            #pragma unroll
            for (int dnp = 0; dnp < 4; dnp++) {
                uint32_t vh4[4];
                uint32_t va = smem_u32(Vhs + (j * 16 + t_r) * ALD + dnp * 16 + t_c);
                ldsm_x4_t(vh4[0], vh4[1], vh4[2], vh4[3], va);
                #pragma unroll
                for (int hf = 0; hf < 2; hf++) {
                    const int dn = dnp * 2 + hf;
                    uint32_t bh2[2] = { vh4[hf*2], vh4[hf*2+1] };
                    mma_f16(oacc[dn], ah, bh2);
                }
            }
        }
    }

    // ---- epilogue: normalize, write fp16 O in [B*T, C] ----
    const int b = bh >> 4, h = bh & 15;
    #pragma unroll
    for (int r = 0; r < 2; r++) {
        const float inv = 1.0f / lsum[r];
        const int row = q0 + w * 16 + (lane >> 2) + r * 8;
        const size_t off = (size_t)(b * TT + row) * CC + h * DD;
        #pragma unroll
        for (int dn = 0; dn < 8; dn++) {
            const int col = dn * 8 + (lane & 3) * 2;
            *(uint32_t*)(g_Oh + off + col) =
                packf2(oacc[dn][2*r] * inv, oacc[dn][2*r+1] * inv);
        }
    }
}

// ---------------------------------------------------------------------------
extern "C" void kernel_launch(void* const* d_in, const int* in_sizes, int n_in,
                              void* d_out, int out_size)
{
    const float* x     = (const float*)d_in[0];
    const float* wqkv  = (const float*)d_in[1];
    const float* wproj = (const float*)d_in[2];
    float* out = (float*)d_out;

    cudaFuncSetAttribute((const void*)attn_mma_kernel,
                         cudaFuncAttributeMaxDynamicSharedMemorySize, ATTN_SMEM_BYTES);
    cudaFuncSetAttribute((const void*)mma_gemm_kernel<0>,
                         cudaFuncAttributeMaxDynamicSharedMemorySize, GEMM_SMEM_BYTES);
    cudaFuncSetAttribute((const void*)mma_gemm_kernel<1>,
                         cudaFuncAttributeMaxDynamicSharedMemorySize, GEMM_SMEM_BYTES);

    __half *xh, *wqh, *wph, *oh;
    cudaGetSymbolAddress((void**)&xh,  g_Xh);
    cudaGetSymbolAddress((void**)&wqh, g_Wqh);
    cudaGetSymbolAddress((void**)&wph, g_Wph);
    cudaGetSymbolAddress((void**)&oh,  g_Oh);

    convert_all_kernel<<<(N4_ALL + 255)/256, 256>>>(x, wqkv, wproj);

    mma_gemm_kernel<0><<<dim3(NQKV/128, MM/128), GEMM_THREADS, GEMM_SMEM_BYTES>>>(
        xh, wqh, nullptr);

    attn_mma_kernel<<<(TT/AQT) * BB * HH, 256, ATTN_SMEM_BYTES>>>();

    mma_gemm_kernel<1><<<dim3(CC/128, MM/128), GEMM_THREADS, GEMM_SMEM_BYTES>>>(
        oh, wph, out);
}

// round 17
// speedup vs baseline: 1.1700x; 1.0006x over previous
#include <cuda_runtime.h>
#include <cuda_fp16.h>
#include <cstdint>
#include <math.h>

// Problem constants
#define BB 4
#define TT 2048
#define CC 1024
#define HH 16
#define DD 64
#define MM (BB*TT)          // 8192
#define NQKV (3*CC)         // 3072

// ---------------------------------------------------------------------------
// Scratch (__device__ globals; no allocation allowed)
// ---------------------------------------------------------------------------
__device__ __half g_Qh[BB*HH*TT*DD];          // fp16, pre-scaled by 0.125*log2(e)
__device__ __half g_Kh[BB*HH*TT*DD];
__device__ __half g_Vh[BB*HH*TT*DD];
__device__ __half g_Xh[MM*CC];                // x as fp16
__device__ __half g_Wqh[NQKV*CC];             // w_qkv fp16
__device__ __half g_Wph[CC*CC];               // w_proj fp16
__device__ __half g_Oh[MM*CC];                // attn out fp16, [B*T, C]

// ---------------------------------------------------------------------------
// helpers
// ---------------------------------------------------------------------------
__device__ __forceinline__ uint32_t smem_u32(const void* p) {
    uint32_t a;
    asm("{ .reg .u64 t; cvta.to.shared.u64 t, %1; cvt.u32.u64 %0, t; }" : "=r"(a) : "l"(p));
    return a;
}
__device__ __forceinline__ void ldsm_x4(uint32_t& r0, uint32_t& r1, uint32_t& r2,
                                        uint32_t& r3, uint32_t addr) {
    asm volatile("ldmatrix.sync.aligned.m8n8.x4.shared.b16 {%0,%1,%2,%3}, [%4];"
                 : "=r"(r0), "=r"(r1), "=r"(r2), "=r"(r3) : "r"(addr));
}
__device__ __forceinline__ void ldsm_x4_t(uint32_t& r0, uint32_t& r1, uint32_t& r2,
                                          uint32_t& r3, uint32_t addr) {
    asm volatile("ldmatrix.sync.aligned.m8n8.x4.trans.shared.b16 {%0,%1,%2,%3}, [%4];"
                 : "=r"(r0), "=r"(r1), "=r"(r2), "=r"(r3) : "r"(addr));
}
__device__ __forceinline__ void mma_f16(float* c, const uint32_t* a, const uint32_t* b) {
    asm volatile("mma.sync.aligned.m16n8k16.row.col.f32.f16.f16.f32 "
                 "{%0,%1,%2,%3}, {%4,%5,%6,%7}, {%8,%9}, {%0,%1,%2,%3};"
                 : "+f"(c[0]), "+f"(c[1]), "+f"(c[2]), "+f"(c[3])
                 : "r"(a[0]), "r"(a[1]), "r"(a[2]), "r"(a[3]), "r"(b[0]), "r"(b[1]));
}
__device__ __forceinline__ void cp16(uint32_t dst, const void* src) {
    asm volatile("cp.async.cg.shared.global [%0], [%1], 16;" :: "r"(dst), "l"(src));
}
#define CP_COMMIT() asm volatile("cp.async.commit_group;" ::: "memory")
#define CP_WAIT(N)  asm volatile("cp.async.wait_group %0;" :: "n"(N) : "memory")

__device__ __forceinline__ uint32_t packf2(float x, float y) {
    __half2 t = __floats2half2_rn(x, y);   // x -> low half
    return *reinterpret_cast<uint32_t*>(&t);
}
__device__ __forceinline__ float ex2(float x) {
    float r;
    asm("ex2.approx.ftz.f32 %0, %1;" : "=f"(r) : "f"(x));
    return r;
}

// ---------------------------------------------------------------------------
// fused fp32 -> fp16 conversion (x, w_qkv, w_proj in one launch)
// ---------------------------------------------------------------------------
#define N4_X    (MM*CC/4)      // 2097152
#define N4_WQ   (NQKV*CC/4)    //  786432
#define N4_WP   (CC*CC/4)      //  262144
#define N4_ALL  (N4_X + N4_WQ + N4_WP)

__global__ __launch_bounds__(256) void convert_all_kernel(
    const float* __restrict__ x, const float* __restrict__ wq,
    const float* __restrict__ wp)
{
    int i = blockIdx.x * blockDim.x + threadIdx.x;
    if (i >= N4_ALL) return;
    const float* src; __half* dst; int j;
    if (i < N4_X)               { src = x;  dst = g_Xh;  j = i; }
    else if (i < N4_X + N4_WQ)  { src = wq; dst = g_Wqh; j = i - N4_X; }
    else                        { src = wp; dst = g_Wph; j = i - N4_X - N4_WQ; }
    float4 v = ((const float4*)src)[j];
    uint2 o;
    o.x = packf2(v.x, v.y);
    o.y = packf2(v.z, v.w);
    ((uint2*)dst)[j] = o;
}

// ---------------------------------------------------------------------------
// HMMA fp16 single-pass GEMM (unchanged): C = Ah*Bh
// 256 threads / 8 warps, warp 32x64, CTA 128x128, BK=64, 3-stage, 2 CTA/SM.
// MODE 0: Q -> fp16 scaled 0.125*log2e, K/V fp16, [B,H,T,D]. MODE 1: fp32 out.
// ---------------------------------------------------------------------------
#define BKG 64
#define LDG_ 72
#define TILEA (128*LDG_)
#define TILEB (128*LDG_)
#define STAGEG (TILEA + TILEB)            // 18432 halves
#define NSTG 3
#define GEMM_SMEM_BYTES (NSTG*STAGEG*2)   // 110592 B
#define GEMM_THREADS 256
#define LOG2E 1.44269504088896f

template<int MODE>
__global__ __launch_bounds__(GEMM_THREADS, 2) void mma_gemm_kernel(
    const __half* __restrict__ Ah, const __half* __restrict__ Bh,
    float* __restrict__ out)
{
    extern __shared__ __half sm[];
    const uint32_t smb = smem_u32(sm);
    const int tid = threadIdx.x;
    const int lane = tid & 31, wid = tid >> 5;
    const int wm = (wid >> 1) * 32;
    const int wn = (wid & 1) * 64;
    const int n0 = blockIdx.x * 128;
    const int m0 = blockIdx.y * 128;

    const __half* Asrc = Ah + (size_t)m0 * CC;
    const __half* Bsrc = Bh + (size_t)n0 * CC;

    const int NCH = CC / BKG;   // 16

    float acc[2][8][4];
    #pragma unroll
    for (int a = 0; a < 2; a++)
        #pragma unroll
        for (int b = 0; b < 8; b++)
            #pragma unroll
            for (int c = 0; c < 4; c++) acc[a][b][c] = 0.0f;

    const int a_m = ((lane >> 3) & 1) * 8 + (lane & 7);
    const int a_k = (lane >> 4) * 8;
    const int b_n = (lane >> 4) * 8 + (lane & 7);
    const int b_k = ((lane >> 3) & 1) * 8;

    auto issue_chunk = [&](int st, int ch) {
        const uint32_t sbase = smb + (uint32_t)st * (STAGEG * 2);
        const int k0 = ch * BKG;
        #pragma unroll
        for (int l = 0; l < 8; l++) {
            const int o = l * GEMM_THREADS + tid;
            const int r = (o >> 3) & 127;
            const int c = (o & 7) * 8;
            if (o < 1024)
                cp16(sbase + (uint32_t)(r * LDG_ + c) * 2,
                     Asrc + (size_t)r * CC + k0 + c);
            else
                cp16(sbase + (uint32_t)(TILEA + r * LDG_ + c) * 2,
                     Bsrc + (size_t)r * CC + k0 + c);
        }
    };

    issue_chunk(0, 0); CP_COMMIT();
    issue_chunk(1, 1); CP_COMMIT();

    int st_cur = 0, st_pf = 2;
    for (int ch = 0; ch < NCH; ch++) {
        CP_WAIT(1);
        __syncthreads();
        if (ch + 2 < NCH) issue_chunk(st_pf, ch + 2);
        CP_COMMIT();

        const uint32_t buf = smb + (uint32_t)st_cur * (STAGEG * 2);
        if (++st_cur == NSTG) st_cur = 0;
        if (++st_pf == NSTG) st_pf = 0;

        #pragma unroll
        for (int kk = 0; kk < BKG; kk += 16) {
            uint32_t aH[2][4], bH[4][4];
            #pragma unroll
            for (int mi = 0; mi < 2; mi++) {
                const int m = wm + mi * 16 + a_m;
                ldsm_x4(aH[mi][0], aH[mi][1], aH[mi][2], aH[mi][3],
                        buf + (uint32_t)(m * LDG_ + kk + a_k) * 2);
            }
            #pragma unroll
            for (int ni = 0; ni < 4; ni++) {
                const int n = wn + ni * 16 + b_n;
                ldsm_x4(bH[ni][0], bH[ni][1], bH[ni][2], bH[ni][3],
                        buf + (uint32_t)(TILEA + n * LDG_ + kk + b_k) * 2);
            }
            #pragma unroll
            for (int mi = 0; mi < 2; mi++)
                #pragma unroll
                for (int nj = 0; nj < 8; nj++) {
                    uint32_t bh[2] = { bH[nj >> 1][(nj & 1) * 2], bH[nj >> 1][(nj & 1) * 2 + 1] };
                    mma_f16(acc[mi][nj], aH[mi], bh);
                }
        }
    }

    if (MODE == 0) {
        const int which = n0 >> 10;
        __half* dst = (which == 0) ? g_Qh : ((which == 1) ? g_Kh : g_Vh);
        const float scl = (which == 0) ? (0.125f * LOG2E) : 1.0f;
        #pragma unroll
        for (int mi = 0; mi < 2; mi++)
            #pragma unroll
            for (int nj = 0; nj < 8; nj++) {
                const int row0 = m0 + wm + mi * 16 + (lane >> 2);
                const int col  = n0 + wn + nj * 8 + (lane & 3) * 2;
                const int o = col & 1023, hd = o >> 6, d = o & 63;
                #pragma unroll
                for (int h = 0; h < 2; h++) {
                    const int row = row0 + h * 8;
                    const int b = row >> 11, t = row & 2047;
                    const size_t off = ((size_t)(b * HH + hd) * TT + t) * DD + d;
                    *(uint32_t*)(dst + off) =
                        packf2(acc[mi][nj][h*2] * scl, acc[mi][nj][h*2+1] * scl);
                }
            }
    } else {
        #pragma unroll
        for (int mi = 0; mi < 2; mi++)
            #pragma unroll
            for (int nj = 0; nj < 8; nj++) {
                const int row0 = m0 + wm + mi * 16 + (lane >> 2);
                const int col  = n0 + wn + nj * 8 + (lane & 3) * 2;
                #pragma unroll
                for (int h = 0; h < 2; h++) {
                    const int row = row0 + h * 8;
                    float2 v = make_float2(acc[mi][nj][h*2], acc[mi][nj][h*2+1]);
                    *(float2*)(out + (size_t)row * CC + col) = v;
                }
            }
    }
}

// ---------------------------------------------------------------------------
// fp16 tensor-core flash attention (causal), exp2 softmax (approx EX2),
// KTILE=64, 4-stage cp.async KV ring, CP_WAIT(2), 1D longest-first grid.
// Fully-masked warps skip tiles; diagonal tiles skip masked 16-key groups
// in both S and PV (exact: skipped S groups get -1e30 mask; skipped PV
// groups have P == exactly 0).
// smem = Q 18.4KB + 4x18.4KB = 92.2KB -> 2 CTA/SM.
// ---------------------------------------------------------------------------
#define AQT 128
#define AKT 64
#define ALD 72
#define ANST 4

struct AttnSmem {
    __half Q[AQT*ALD];
    __half KV[ANST][2][AKT*ALD];       // stage, {Kh,Vh}
};
#define ATTN_SMEM_BYTES ((int)sizeof(AttnSmem))   // 92160

__global__ __launch_bounds__(256, 2) void attn_mma_kernel()
{
    extern __shared__ char smraw[];
    AttnSmem& s = *(AttnSmem*)smraw;

    const int tid = threadIdx.x, lane = tid & 31, w = tid >> 5;
    // 1D grid, global longest-first: bid 0..1023 -> qi 15..0 (outer), bh 0..63
    const int bid = blockIdx.x;
    const int qi = (TT/AQT - 1) - (bid >> 6);
    const int bh = bid & 63;
    const int q0 = qi * AQT;
    const size_t base = (size_t)bh * TT * DD;
    const __half* kvsrc[2] = { g_Kh + base, g_Vh + base };
    const __half* Qsrc = g_Qh + base;

    const int nk = 2 * qi + 2;

    const int kr0 = tid >> 3, kr1 = 32 + (tid >> 3);
    const int kc = (tid & 7) * 8;

    auto issue_kv = [&](int st, int kt) {
        const int k0 = kt * AKT;
        #pragma unroll
        for (int t = 0; t < 2; t++) {
            cp16(smem_u32(&s.KV[st][t][kr0 * ALD + kc]),
                 kvsrc[t] + (size_t)(k0 + kr0) * DD + kc);
            cp16(smem_u32(&s.KV[st][t][kr1 * ALD + kc]),
                 kvsrc[t] + (size_t)(k0 + kr1) * DD + kc);
        }
    };

    // prologue: prefetch up to 3 tiles (nk >= 2 always)
    issue_kv(0, 0); CP_COMMIT();
    issue_kv(1, 1); CP_COMMIT();
    if (2 < nk) issue_kv(2, 2);
    CP_COMMIT();

    #pragma unroll
    for (int l = 0; l < 4; l++) {
        int idx = l * 256 + tid;
        int r = idx >> 3, d0 = (idx & 7) * 8;
        *(uint4*)&s.Q[r * ALD + d0] = *(const uint4*)(Qsrc + (size_t)(q0 + r) * DD + d0);
    }
    __syncthreads();

    const int a_m = ((lane >> 3) & 1) * 8 + (lane & 7);
    const int a_k = (lane >> 4) * 8;
    const int b_n = (lane >> 4) * 8 + (lane & 7);
    const int b_k = ((lane >> 3) & 1) * 8;
    const int t_r = ((lane >> 3) & 1) * 8 + (lane & 7);
    const int t_c = (lane >> 4) * 8;

    uint32_t qh[4][4];
    #pragma unroll
    for (int ks = 0; ks < 4; ks++) {
        uint32_t qa = smem_u32(&s.Q[(w * 16 + a_m) * ALD + ks * 16 + a_k]);
        ldsm_x4(qh[ks][0], qh[ks][1], qh[ks][2], qh[ks][3], qa);
    }

    float oacc[8][4];
    #pragma unroll
    for (int i = 0; i < 8; i++)
        #pragma unroll
        for (int j = 0; j < 4; j++) oacc[i][j] = 0.0f;
    float mrun[2] = { -1e30f, -1e30f }, lsum[2] = { 0.0f, 0.0f };

    const int qrow = q0 + w * 16 + (lane >> 2);
    const int wrow_max = q0 + w * 16 + 15;     // largest q-row this warp owns

    int st_cur = 0, st_pf = 3;
    for (int kt = 0; kt < nk; kt++) {
        const int k0 = kt * AKT;
        CP_WAIT(2);
        __syncthreads();
        if (kt + 3 < nk) issue_kv(st_pf, kt + 3);
        CP_COMMIT();

        const __half* Khs = s.KV[st_cur][0];
        const __half* Vhs = s.KV[st_cur][1];
        if (++st_cur == ANST) st_cur = 0;
        if (++st_pf == ANST) st_pf = 0;

        // Fully-masked warp skip (warp-uniform; barriers are outside).
        if (k0 > wrow_max) continue;

        // ---- S = Q K^T (Q carries 0.125*log2e); skip fully-masked 16-key
        //      groups (sacc stays 0; mask overwrites with -1e30) ----
        float sacc[8][4];
        #pragma unroll
        for (int i = 0; i < 8; i++)
            #pragma unroll
            for (int j = 0; j < 4; j++) sacc[i][j] = 0.0f;

        #pragma unroll
        for (int nbp = 0; nbp < 4; nbp++) {
            if (k0 + nbp * 16 <= wrow_max) {
                #pragma unroll
                for (int ks = 0; ks < 4; ks++) {
                    uint32_t kh4[4];
                    uint32_t ka = smem_u32(Khs + (nbp * 16 + b_n) * ALD + ks * 16 + b_k);
                    ldsm_x4(kh4[0], kh4[1], kh4[2], kh4[3], ka);
                    #pragma unroll
                    for (int hf = 0; hf < 2; hf++) {
                        const int nb = nbp * 2 + hf;
                        uint32_t bh2[2] = { kh4[hf*2], kh4[hf*2+1] };
                        mma_f16(sacc[nb], qh[ks], bh2);
                    }
                }
            }
        }

        // ---- causal mask ----
        if (k0 + 63 > qrow) {
            #pragma unroll
            for (int nb = 0; nb < 8; nb++)
                #pragma unroll
                for (int c = 0; c < 4; c++) {
                    const int kg = k0 + nb * 8 + (lane & 3) * 2 + (c & 1);
                    const int qg = qrow + ((c >= 2) ? 8 : 0);
                    if (kg > qg) sacc[nb][c] = -1e30f;
                }
        }

        // ---- online softmax (base-2, approx EX2) ----
        #pragma unroll
        for (int r = 0; r < 2; r++) {
            float tm = -1e30f;
            #pragma unroll
            for (int nb = 0; nb < 8; nb++)
                tm = fmaxf(tm, fmaxf(sacc[nb][2*r], sacc[nb][2*r+1]));
            tm = fmaxf(tm, __shfl_xor_sync(0xffffffffu, tm, 1));
            tm = fmaxf(tm, __shfl_xor_sync(0xffffffffu, tm, 2));
            const float mn = fmaxf(mrun[r], tm);
            const float al = ex2(mrun[r] - mn);
            mrun[r] = mn;
            float rs = 0.0f;
            #pragma unroll
            for (int nb = 0; nb < 8; nb++) {
                float p0 = ex2(sacc[nb][2*r]   - mn);
                float p1 = ex2(sacc[nb][2*r+1] - mn);
                sacc[nb][2*r] = p0; sacc[nb][2*r+1] = p1;
                rs += p0 + p1;
            }
            rs += __shfl_xor_sync(0xffffffffu, rs, 1);
            rs += __shfl_xor_sync(0xffffffffu, rs, 2);
            lsum[r] = lsum[r] * al + rs;
            #pragma unroll
            for (int dn = 0; dn < 8; dn++) {
                oacc[dn][2*r] *= al; oacc[dn][2*r+1] *= al;
            }
        }

        // ---- O += P V (trans-ldmatrix V); skip groups where P == 0 exactly ----
        #pragma unroll
        for (int j = 0; j < 4; j++) {
            if (k0 + j * 16 > wrow_max) continue;   // whole group masked -> P=0
            uint32_t ah[4];
            ah[0] = packf2(sacc[2*j][0],   sacc[2*j][1]);
            ah[1] = packf2(sacc[2*j][2],   sacc[2*j][3]);
            ah[2] = packf2(sacc[2*j+1][0], sacc[2*j+1][1]);
            ah[3] = packf2(sacc[2*j+1][2], sacc[2*j+1][3]);
            #pragma unroll
            for (int dnp = 0; dnp < 4; dnp++) {
                uint32_t vh4[4];
                uint32_t va = smem_u32(Vhs + (j * 16 + t_r) * ALD + dnp * 16 + t_c);
                ldsm_x4_t(vh4[0], vh4[1], vh4[2], vh4[3], va);
                #pragma unroll
                for (int hf = 0; hf < 2; hf++) {
                    const int dn = dnp * 2 + hf;
                    uint32_t bh2[2] = { vh4[hf*2], vh4[hf*2+1] };
                    mma_f16(oacc[dn], ah, bh2);
                }
            }
        }
    }

    // ---- epilogue: normalize, write fp16 O in [B*T, C] ----
    const int b = bh >> 4, h = bh & 15;
    #pragma unroll
    for (int r = 0; r < 2; r++) {
        const float inv = 1.0f / lsum[r];
        const int row = q0 + w * 16 + (lane >> 2) + r * 8;
        const size_t off = (size_t)(b * TT + row) * CC + h * DD;
        #pragma unroll
        for (int dn = 0; dn < 8; dn++) {
            const int col = dn * 8 + (lane & 3) * 2;
            *(uint32_t*)(g_Oh + off + col) =
                packf2(oacc[dn][2*r] * inv, oacc[dn][2*r+1] * inv);
        }
    }
}

// ---------------------------------------------------------------------------
extern "C" void kernel_launch(void* const* d_in, const int* in_sizes, int n_in,
                              void* d_out, int out_size)
{
    const float* x     = (const float*)d_in[0];
    const float* wqkv  = (const float*)d_in[1];
    const float* wproj = (const float*)d_in[2];
    float* out = (float*)d_out;

    cudaFuncSetAttribute((const void*)attn_mma_kernel,
                         cudaFuncAttributeMaxDynamicSharedMemorySize, ATTN_SMEM_BYTES);
    cudaFuncSetAttribute((const void*)mma_gemm_kernel<0>,
                         cudaFuncAttributeMaxDynamicSharedMemorySize, GEMM_SMEM_BYTES);
    cudaFuncSetAttribute((const void*)mma_gemm_kernel<1>,
                         cudaFuncAttributeMaxDynamicSharedMemorySize, GEMM_SMEM_BYTES);

    __half *xh, *wqh, *wph, *oh;
    cudaGetSymbolAddress((void**)&xh,  g_Xh);
    cudaGetSymbolAddress((void**)&wqh, g_Wqh);
    cudaGetSymbolAddress((void**)&wph, g_Wph);
    cudaGetSymbolAddress((void**)&oh,  g_Oh);

    convert_all_kernel<<<(N4_ALL + 255)/256, 256>>>(x, wqkv, wproj);

    mma_gemm_kernel<0><<<dim3(NQKV/128, MM/128), GEMM_THREADS, GEMM_SMEM_BYTES>>>(
        xh, wqh, nullptr);

    attn_mma_kernel<<<(TT/AQT) * BB * HH, 256, ATTN_SMEM_BYTES>>>();

    mma_gemm_kernel<1><<<dim3(CC/128, MM/128), GEMM_THREADS, GEMM_SMEM_BYTES>>>(
        oh, wph, out);
}